// round 11
// baseline (speedup 1.0000x reference)
#include <cuda_runtime.h>
#include <cuda_bf16.h>
#include <cstdint>

#define CH 512
#define LC (96 * 512)      // 49152

// Static device scratch (allocation-free per harness rules).
__device__ float g_xp80[80 * LC];
__device__ float g_cp80[80 * LC];
__device__ float g_xp16[16 * LC];
__device__ float g_cp16[16 * LC];
__device__ float g_A80 [80 * LC];
__device__ float g_A16 [16 * LC];

// ---------------------------------------------------------------------------
// helpers
// ---------------------------------------------------------------------------
__device__ __forceinline__ uint32_t smem_u32(const void* p) {
    uint32_t a;
    asm("{ .reg .u64 t; cvta.to.shared.u64 t, %1; cvt.u32.u64 %0, t; }"
        : "=r"(a) : "l"(p));
    return a;
}

#define LDSM_X4(r0, r1, r2, r3, addr) \
    asm volatile("ldmatrix.sync.aligned.m8n8.x4.shared.b16 {%0,%1,%2,%3}, [%4];" \
                 : "=r"(r0), "=r"(r1), "=r"(r2), "=r"(r3) : "r"(addr))
#define LDSM_X4T(r0, r1, r2, r3, addr) \
    asm volatile("ldmatrix.sync.aligned.m8n8.x4.trans.shared.b16 {%0,%1,%2,%3}, [%4];" \
                 : "=r"(r0), "=r"(r1), "=r"(r2), "=r"(r3) : "r"(addr))

__device__ __forceinline__ void mma16816(float* d, uint32_t a0, uint32_t a1,
                                         uint32_t a2, uint32_t a3,
                                         uint32_t b0, uint32_t b1) {
    asm volatile("mma.sync.aligned.m16n8k16.row.col.f32.bf16.bf16.f32 "
                 "{%0,%1,%2,%3}, {%4,%5,%6,%7}, {%8,%9}, {%0,%1,%2,%3};"
                 : "+f"(d[0]), "+f"(d[1]), "+f"(d[2]), "+f"(d[3])
                 : "r"(a0), "r"(a1), "r"(a2), "r"(a3), "r"(b0), "r"(b1));
}

#define STS64V(addr, a, b) \
    asm volatile("st.shared.v2.b32 [%0], {%1,%2};" :: "r"(addr), "r"(a), "r"(b) : "memory")

// bf16 hi/lo split (scalar)
__device__ __forceinline__ void bsplit(float v, uint32_t& h, uint32_t& l) {
    __nv_bfloat16 hb = __float2bfloat16(v);
    float r = v - __bfloat162float(hb);
    __nv_bfloat16 lb = __float2bfloat16(r);
    h = (uint32_t)__bfloat16_as_ushort(hb);
    l = (uint32_t)__bfloat16_as_ushort(lb);
}
// pack two floats to bf16x2 hi/lo pair (v0 -> low 16 bits)
__device__ __forceinline__ void bpack2(float v0, float v1,
                                       uint32_t& hi, uint32_t& lo) {
    uint32_t h0, l0, h1, l1;
    bsplit(v0, h0, l0); bsplit(v1, h1, l1);
    hi = h0 | (h1 << 16);
    lo = l0 | (l1 << 16);
}

// ---------------------------------------------------------------------------
// 5-way mean pools (two-stage; level-16 derived from level-80 buffer)
// ---------------------------------------------------------------------------
__global__ void pool5_from_input(const float* __restrict__ x,
                                 const float* __restrict__ cr) {
    int t = blockIdx.x * blockDim.x + threadIdx.x;
    const int per = LC / 4;
    if (t >= 80 * per) return;
    int g = t / per, m = t - g * per;
    const float4* xa = (const float4*)x;
    const float4* ca = (const float4*)cr;
    float4 sx = make_float4(0, 0, 0, 0), sc = make_float4(0, 0, 0, 0);
#pragma unroll
    for (int j = 0; j < 5; j++) {
        float4 a = xa[(g * 5 + j) * per + m], b = ca[(g * 5 + j) * per + m];
        sx.x += a.x; sx.y += a.y; sx.z += a.z; sx.w += a.w;
        sc.x += b.x; sc.y += b.y; sc.z += b.z; sc.w += b.w;
    }
    const float s = 0.2f;
    sx.x *= s; sx.y *= s; sx.z *= s; sx.w *= s;
    sc.x *= s; sc.y *= s; sc.z *= s; sc.w *= s;
    ((float4*)g_xp80)[g * per + m] = sx;
    ((float4*)g_cp80)[g * per + m] = sc;
}

__global__ void pool5_level2() {
    int t = blockIdx.x * blockDim.x + threadIdx.x;
    const int per = LC / 4;
    if (t >= 16 * per) return;
    int g = t / per, m = t - g * per;
    const float4* xa = (const float4*)g_xp80;
    const float4* ca = (const float4*)g_cp80;
    float4 sx = make_float4(0, 0, 0, 0), sc = make_float4(0, 0, 0, 0);
#pragma unroll
    for (int j = 0; j < 5; j++) {
        float4 a = xa[(g * 5 + j) * per + m], b = ca[(g * 5 + j) * per + m];
        sx.x += a.x; sx.y += a.y; sx.z += a.z; sx.w += a.w;
        sc.x += b.x; sc.y += b.y; sc.z += b.z; sc.w += b.w;
    }
    const float s = 0.2f;
    sx.x *= s; sx.y *= s; sx.z *= s; sx.w *= s;
    sc.x *= s; sc.y *= s; sc.z *= s; sc.w *= s;
    ((float4*)g_xp16)[g * per + m] = sx;
    ((float4*)g_cp16)[g * per + m] = sc;
}

// ---------------------------------------------------------------------------
// Smem layout (bytes).
// Phase 1: QHI/QLO/KHI/KLO, 96 rows x 144 B stride (64 ch bf16), 4 x 13824.
// Phase 3: double-buffered VHI/VLO pairs: buf0 @ 0/13824, buf1 @ 27648/41472.
// Total 55296 -> 4 CTAs/SM.
// ---------------------------------------------------------------------------
#define QSTR 144
#define SM_QHI 0u
#define SM_QLO 13824u
#define SM_KHI 27648u
#define SM_KLO 41472u      // end: 55296
#define VBUF_STRIDE 27648u // buf k at k*27648; HI at +0, LO at +13824
#define SMEM_TOTAL 55296

// ---------------------------------------------------------------------------
// mma.sync bf16 hi/lo attention; softmax weights stay in registers as
// A-fragments for GEMM2.
// FUSED=false: pooled jobs (jid = blockIdx.x in [0,96)).
// FUSED=true : raw jobs (b = blockIdx.x), epilogue fuses the hierarchical
//              combine (kernel-boundary ordering; no flags).
// One CTA = one job. 192 threads = 6 warps; warp w owns M rows [16w,16w+16).
// ---------------------------------------------------------------------------
template <bool FUSED>
__global__ void __launch_bounds__(192, 4)
attn_mma(const float* __restrict__ x, const float* __restrict__ cross,
         float* out) {
    extern __shared__ char smem[];
    const uint32_t sb = smem_u32(smem);
    const int tid = threadIdx.x;
    const int w   = tid >> 5;
    const int l   = tid & 31;

    const float *q, *kv;
    float* o;
    int b;
    if (FUSED) {
        b = blockIdx.x;  q = x; kv = cross; o = out;
    } else {
        const int jid = blockIdx.x;
        if (jid < 16) { q = g_xp16; kv = g_cp16; o = g_A16; b = jid; }
        else          { q = g_xp80; kv = g_cp80; o = g_A80; b = jid - 16; }
    }
    const float* qb = q  + (size_t)b * LC;
    const float* kb = kv + (size_t)b * LC;
    float*       ob = o  + (size_t)b * LC;
    const float* a16b = FUSED ? (g_A16 + (size_t)(b / 25) * LC) : nullptr;
    const float* a80b = FUSED ? (g_A80 + (size_t)(b / 5)  * LC) : nullptr;

    const int m0 = w * 16;
    // ldmatrix lane->address components
    const uint32_t x4off = (uint32_t)((l & 7) + ((l >> 4) & 1) * 8) * QSTR
                         + ((l >> 3) & 1) * 16;                        // K tiles
    const uint32_t aoffQ = (uint32_t)(m0 + (l & 7) + ((l >> 3) & 1) * 8) * QSTR
                         + ((l >> 4) & 1) * 16;
    const uint32_t boffV4 = (uint32_t)((l & 15) * QSTR + ((l >> 4) & 1) * 16);

    // ==== Phase 1: S = Q K^T, K-chunks of 64 channels ========================
    float acc[12][4];
#pragma unroll
    for (int n = 0; n < 12; n++)
#pragma unroll
        for (int u = 0; u < 4; u++) acc[n][u] = 0.f;

    for (int ck = 0; ck < 8; ck++) {
        const int kc = ck * 64;
        __syncthreads();   // prev chunk's mma reads done
#pragma unroll
        for (int i = 0; i < 8; i++) {
            int idx = tid + 192 * i;      // 0..1535 float4 slots
            int row = idx >> 4, c4 = idx & 15;
            uint32_t a = (uint32_t)(row * QSTR + c4 * 8);
            float4 qv = *(const float4*)(qb + row * CH + kc + c4 * 4);
            uint32_t p0h, p0l, p1h, p1l;
            bpack2(qv.x, qv.y, p0h, p0l);
            bpack2(qv.z, qv.w, p1h, p1l);
            STS64V(sb + SM_QHI + a, p0h, p1h);
            STS64V(sb + SM_QLO + a, p0l, p1l);
            float4 kv4 = *(const float4*)(kb + row * CH + kc + c4 * 4);
            bpack2(kv4.x, kv4.y, p0h, p0l);
            bpack2(kv4.z, kv4.w, p1h, p1l);
            STS64V(sb + SM_KHI + a, p0h, p1h);
            STS64V(sb + SM_KLO + a, p0l, p1l);
        }
        __syncthreads();
#pragma unroll
        for (int ks = 0; ks < 4; ks++) {
            const uint32_t kB = (uint32_t)(ks * 32);  // 16 ch = 32 B
            uint32_t ah0,ah1,ah2,ah3, al0,al1,al2,al3;
            LDSM_X4(ah0,ah1,ah2,ah3, sb + SM_QHI + aoffQ + kB);
            LDSM_X4(al0,al1,al2,al3, sb + SM_QLO + aoffQ + kB);
#pragma unroll
            for (int n2 = 0; n2 < 6; n2++) {
                uint32_t ba = sb + SM_KHI + (uint32_t)(n2 * 16 * QSTR) + x4off + kB;
                uint32_t bh0,bh1,bh2,bh3, bl0,bl1,bl2,bl3;
                LDSM_X4(bh0,bh1,bh2,bh3, ba);
                LDSM_X4(bl0,bl1,bl2,bl3, ba + (SM_KLO - SM_KHI));
                mma16816(acc[2*n2],   ah0,ah1,ah2,ah3, bh0,bh1);
                mma16816(acc[2*n2],   ah0,ah1,ah2,ah3, bl0,bl1);
                mma16816(acc[2*n2],   al0,al1,al2,al3, bh0,bh1);
                mma16816(acc[2*n2+1], ah0,ah1,ah2,ah3, bh2,bh3);
                mma16816(acc[2*n2+1], ah0,ah1,ah2,ah3, bl2,bl3);
                mma16816(acc[2*n2+1], al0,al1,al2,al3, bh2,bh3);
            }
        }
    }
    __syncthreads();   // all mma done; smem free for V

    // ==== Phase 2: softmax in registers -> A-fragments in registers ==========
    uint32_t whi[24], wlo[24];
    {
        const float scale = 0.04419417382415922f;  // 1/sqrt(512)
        float mx0 = -3.4e38f, mx1 = -3.4e38f;
#pragma unroll
        for (int n = 0; n < 12; n++) {
#pragma unroll
            for (int u = 0; u < 4; u++) acc[n][u] *= scale;
            mx0 = fmaxf(mx0, fmaxf(acc[n][0], acc[n][1]));
            mx1 = fmaxf(mx1, fmaxf(acc[n][2], acc[n][3]));
        }
        mx0 = fmaxf(mx0, __shfl_xor_sync(0xffffffffu, mx0, 1));
        mx0 = fmaxf(mx0, __shfl_xor_sync(0xffffffffu, mx0, 2));
        mx1 = fmaxf(mx1, __shfl_xor_sync(0xffffffffu, mx1, 1));
        mx1 = fmaxf(mx1, __shfl_xor_sync(0xffffffffu, mx1, 2));
        float s0 = 0.f, s1 = 0.f;
#pragma unroll
        for (int n = 0; n < 12; n++) {
            acc[n][0] = __expf(acc[n][0] - mx0); s0 += acc[n][0];
            acc[n][1] = __expf(acc[n][1] - mx0); s0 += acc[n][1];
            acc[n][2] = __expf(acc[n][2] - mx1); s1 += acc[n][2];
            acc[n][3] = __expf(acc[n][3] - mx1); s1 += acc[n][3];
        }
        s0 += __shfl_xor_sync(0xffffffffu, s0, 1);
        s0 += __shfl_xor_sync(0xffffffffu, s0, 2);
        s1 += __shfl_xor_sync(0xffffffffu, s1, 1);
        s1 += __shfl_xor_sync(0xffffffffu, s1, 2);
        float i0 = 1.f / s0, i1 = 1.f / s1;
#pragma unroll
        for (int ks = 0; ks < 6; ks++) {
            bpack2(acc[2*ks][0] * i0,   acc[2*ks][1] * i0,   whi[4*ks+0], wlo[4*ks+0]);
            bpack2(acc[2*ks][2] * i1,   acc[2*ks][3] * i1,   whi[4*ks+1], wlo[4*ks+1]);
            bpack2(acc[2*ks+1][0] * i0, acc[2*ks+1][1] * i0, whi[4*ks+2], wlo[4*ks+2]);
            bpack2(acc[2*ks+1][2] * i1, acc[2*ks+1][3] * i1, whi[4*ks+3], wlo[4*ks+3]);
        }
    }

    // ==== Phase 3: O = W V, double-buffered 64-ch chunks =====================
    // preload chunk 0 -> buf0
    {
#pragma unroll
        for (int i = 0; i < 8; i++) {
            int idx = tid + 192 * i;
            int row = idx >> 4, c4 = idx & 15;
            uint32_t a = (uint32_t)(row * QSTR + c4 * 8);
            float4 vv = *(const float4*)(kb + row * CH + c4 * 4);
            uint32_t p0h, p0l, p1h, p1l;
            bpack2(vv.x, vv.y, p0h, p0l);
            bpack2(vv.z, vv.w, p1h, p1l);
            STS64V(sb + a, p0h, p1h);
            STS64V(sb + 13824u + a, p0l, p1l);
        }
    }
    __syncthreads();

    for (int ci = 0; ci < 8; ci++) {
        const uint32_t bufR = (uint32_t)(ci & 1) * VBUF_STRIDE;
        // stage chunk ci+1 into the other buffer (overlaps this chunk's mma
        // across warps; different buffer so no hazard)
        if (ci < 7) {
            const int cc = (ci + 1) * 64;
            const uint32_t bufW = (uint32_t)((ci + 1) & 1) * VBUF_STRIDE;
#pragma unroll
            for (int i = 0; i < 8; i++) {
                int idx = tid + 192 * i;
                int row = idx >> 4, c4 = idx & 15;
                uint32_t a = (uint32_t)(row * QSTR + c4 * 8);
                float4 vv = *(const float4*)(kb + row * CH + cc + c4 * 4);
                uint32_t p0h, p0l, p1h, p1l;
                bpack2(vv.x, vv.y, p0h, p0l);
                bpack2(vv.z, vv.w, p1h, p1l);
                STS64V(sb + bufW + a, p0h, p1h);
                STS64V(sb + bufW + 13824u + a, p0l, p1l);
            }
        }

        const int cc = ci * 64;
#pragma unroll
        for (int h = 0; h < 2; h++) {
            float acc2[4][4];
#pragma unroll
            for (int n = 0; n < 4; n++)
#pragma unroll
                for (int u = 0; u < 4; u++) acc2[n][u] = 0.f;

#pragma unroll
            for (int ks = 0; ks < 6; ks++) {
                const uint32_t vR = (uint32_t)(ks * 16 * QSTR);
#pragma unroll
                for (int n2 = 0; n2 < 2; n2++) {
                    uint32_t ba = sb + bufR + vR + boffV4
                                + (uint32_t)(h * 64 + n2 * 32);
                    uint32_t bh0,bh1,bh2,bh3, bl0,bl1,bl2,bl3;
                    LDSM_X4T(bh0,bh1,bh2,bh3, ba);
                    LDSM_X4T(bl0,bl1,bl2,bl3, ba + 13824u);
                    mma16816(acc2[2*n2],   whi[4*ks],whi[4*ks+1],whi[4*ks+2],whi[4*ks+3], bh0,bh1);
                    mma16816(acc2[2*n2],   whi[4*ks],whi[4*ks+1],whi[4*ks+2],whi[4*ks+3], bl0,bl1);
                    mma16816(acc2[2*n2],   wlo[4*ks],wlo[4*ks+1],wlo[4*ks+2],wlo[4*ks+3], bh0,bh1);
                    mma16816(acc2[2*n2+1], whi[4*ks],whi[4*ks+1],whi[4*ks+2],whi[4*ks+3], bh2,bh3);
                    mma16816(acc2[2*n2+1], whi[4*ks],whi[4*ks+1],whi[4*ks+2],whi[4*ks+3], bl2,bl3);
                    mma16816(acc2[2*n2+1], wlo[4*ks],wlo[4*ks+1],wlo[4*ks+2],wlo[4*ks+3], bh2,bh3);
                }
            }
            {
                const int g  = l >> 2;
                const int i4 = l & 3;
                const int r0 = m0 + g, r1 = r0 + 8;
                const float c43 = 4.0f / 3.0f, c13 = 1.0f / 3.0f;
#pragma unroll
                for (int n = 0; n < 4; n++) {
                    int col = cc + h * 32 + n * 8 + 2 * i4;
                    float2 v0 = make_float2(acc2[n][0], acc2[n][1]);
                    float2 v1 = make_float2(acc2[n][2], acc2[n][3]);
                    if (FUSED) {
                        size_t o0 = (size_t)r0 * CH + col;
                        size_t o1 = (size_t)r1 * CH + col;
                        float2 p0 = *(const float2*)(a16b + o0);
                        float2 q0 = *(const float2*)(a80b + o0);
                        float2 p1 = *(const float2*)(a16b + o1);
                        float2 q1 = *(const float2*)(a80b + o1);
                        v0.x = c43 * v0.x + c13 * (p0.x + q0.x);
                        v0.y = c43 * v0.y + c13 * (p0.y + q0.y);
                        v1.x = c43 * v1.x + c13 * (p1.x + q1.x);
                        v1.y = c43 * v1.y + c13 * (p1.y + q1.y);
                    }
                    *(float2*)(ob + (size_t)r0 * CH + col) = v0;
                    *(float2*)(ob + (size_t)r1 * CH + col) = v1;
                }
            }
        }
        __syncthreads();   // buf[ci&1] reads done before it is refilled
    }
}

// ---------------------------------------------------------------------------
extern "C" void kernel_launch(void* const* d_in, const int* in_sizes, int n_in,
                              void* d_out, int out_size) {
    const float* x     = (const float*)d_in[0];
    const float* cross = (const float*)d_in[1];
    float*       out   = (float*)d_out;

    static bool init_done = false;
    if (!init_done) {
        cudaFuncSetAttribute(attn_mma<false>,
                             cudaFuncAttributeMaxDynamicSharedMemorySize, SMEM_TOTAL);
        cudaFuncSetAttribute(attn_mma<true>,
                             cudaFuncAttributeMaxDynamicSharedMemorySize, SMEM_TOTAL);
        init_done = true;
    }

    {
        int total = 80 * (LC / 4);
        pool5_from_input<<<(total + 255) / 256, 256>>>(x, cross);
    }
    {
        int total = 16 * (LC / 4);
        pool5_level2<<<(total + 255) / 256, 256>>>();
    }
    // Pooled jobs first (writes g_A16/g_A80), then raw jobs with fused combine.
    attn_mma<false><<<96, 192, SMEM_TOTAL>>>(x, cross, out);
    attn_mma<true><<<400, 192, SMEM_TOTAL>>>(x, cross, out);
}

// round 12
// speedup vs baseline: 1.2094x; 1.2094x over previous
#include <cuda_runtime.h>
#include <cuda_bf16.h>
#include <cstdint>

#define CH 512
#define LC (96 * 512)      // 49152

// Static device scratch (allocation-free per harness rules).
__device__ float g_xp80[80 * LC];
__device__ float g_cp80[80 * LC];
__device__ float g_xp16[16 * LC];
__device__ float g_cp16[16 * LC];
__device__ float g_A80 [80 * LC];
__device__ float g_A16 [16 * LC];

// ---------------------------------------------------------------------------
// helpers
// ---------------------------------------------------------------------------
__device__ __forceinline__ uint32_t smem_u32(const void* p) {
    uint32_t a;
    asm("{ .reg .u64 t; cvta.to.shared.u64 t, %1; cvt.u32.u64 %0, t; }"
        : "=r"(a) : "l"(p));
    return a;
}

#define LDSM_X4(r0, r1, r2, r3, addr) \
    asm volatile("ldmatrix.sync.aligned.m8n8.x4.shared.b16 {%0,%1,%2,%3}, [%4];" \
                 : "=r"(r0), "=r"(r1), "=r"(r2), "=r"(r3) : "r"(addr))
#define LDSM_X4T(r0, r1, r2, r3, addr) \
    asm volatile("ldmatrix.sync.aligned.m8n8.x4.trans.shared.b16 {%0,%1,%2,%3}, [%4];" \
                 : "=r"(r0), "=r"(r1), "=r"(r2), "=r"(r3) : "r"(addr))

__device__ __forceinline__ void mma16816(float* d, uint32_t a0, uint32_t a1,
                                         uint32_t a2, uint32_t a3,
                                         uint32_t b0, uint32_t b1) {
    asm volatile("mma.sync.aligned.m16n8k16.row.col.f32.bf16.bf16.f32 "
                 "{%0,%1,%2,%3}, {%4,%5,%6,%7}, {%8,%9}, {%0,%1,%2,%3};"
                 : "+f"(d[0]), "+f"(d[1]), "+f"(d[2]), "+f"(d[3])
                 : "r"(a0), "r"(a1), "r"(a2), "r"(a3), "r"(b0), "r"(b1));
}

#define STS64V(addr, a, b) \
    asm volatile("st.shared.v2.b32 [%0], {%1,%2};" :: "r"(addr), "r"(a), "r"(b) : "memory")

// bf16 hi/lo split (scalar)
__device__ __forceinline__ void bsplit(float v, uint32_t& h, uint32_t& l) {
    __nv_bfloat16 hb = __float2bfloat16(v);
    float r = v - __bfloat162float(hb);
    __nv_bfloat16 lb = __float2bfloat16(r);
    h = (uint32_t)__bfloat16_as_ushort(hb);
    l = (uint32_t)__bfloat16_as_ushort(lb);
}
// pack two floats to bf16x2 hi/lo pair (v0 -> low 16 bits)
__device__ __forceinline__ void bpack2(float v0, float v1,
                                       uint32_t& hi, uint32_t& lo) {
    uint32_t h0, l0, h1, l1;
    bsplit(v0, h0, l0); bsplit(v1, h1, l1);
    hi = h0 | (h1 << 16);
    lo = l0 | (l1 << 16);
}

// ---------------------------------------------------------------------------
// 5-way mean pools (two-stage; level-16 derived from level-80 buffer)
// ---------------------------------------------------------------------------
__global__ void pool5_from_input(const float* __restrict__ x,
                                 const float* __restrict__ cr) {
    int t = blockIdx.x * blockDim.x + threadIdx.x;
    const int per = LC / 4;
    if (t >= 80 * per) return;
    int g = t / per, m = t - g * per;
    const float4* xa = (const float4*)x;
    const float4* ca = (const float4*)cr;
    float4 sx = make_float4(0, 0, 0, 0), sc = make_float4(0, 0, 0, 0);
#pragma unroll
    for (int j = 0; j < 5; j++) {
        float4 a = xa[(g * 5 + j) * per + m], b = ca[(g * 5 + j) * per + m];
        sx.x += a.x; sx.y += a.y; sx.z += a.z; sx.w += a.w;
        sc.x += b.x; sc.y += b.y; sc.z += b.z; sc.w += b.w;
    }
    const float s = 0.2f;
    sx.x *= s; sx.y *= s; sx.z *= s; sx.w *= s;
    sc.x *= s; sc.y *= s; sc.z *= s; sc.w *= s;
    ((float4*)g_xp80)[g * per + m] = sx;
    ((float4*)g_cp80)[g * per + m] = sc;
}

__global__ void pool5_level2() {
    int t = blockIdx.x * blockDim.x + threadIdx.x;
    const int per = LC / 4;
    if (t >= 16 * per) return;
    int g = t / per, m = t - g * per;
    const float4* xa = (const float4*)g_xp80;
    const float4* ca = (const float4*)g_cp80;
    float4 sx = make_float4(0, 0, 0, 0), sc = make_float4(0, 0, 0, 0);
#pragma unroll
    for (int j = 0; j < 5; j++) {
        float4 a = xa[(g * 5 + j) * per + m], b = ca[(g * 5 + j) * per + m];
        sx.x += a.x; sx.y += a.y; sx.z += a.z; sx.w += a.w;
        sc.x += b.x; sc.y += b.y; sc.z += b.z; sc.w += b.w;
    }
    const float s = 0.2f;
    sx.x *= s; sx.y *= s; sx.z *= s; sx.w *= s;
    sc.x *= s; sc.y *= s; sc.z *= s; sc.w *= s;
    ((float4*)g_xp16)[g * per + m] = sx;
    ((float4*)g_cp16)[g * per + m] = sc;
}

// ---------------------------------------------------------------------------
// Smem layout (bytes).
// Phase 1: QHI/QLO/KHI/KLO, 96 rows x 144 B stride (64 ch bf16), 4 x 13824.
// Phase 3: double-buffered VHI/VLO pairs: buf0 @ 0/13824, buf1 @ 27648/41472.
// Total 55296 -> 4 CTAs/SM.
// ---------------------------------------------------------------------------
#define QSTR 144
#define SM_QHI 0u
#define SM_QLO 13824u
#define SM_KHI 27648u
#define SM_KLO 41472u      // end: 55296
#define VBUF_STRIDE 27648u // buf k at k*27648; HI at +0, LO at +13824
#define SMEM_TOTAL 55296

// ---------------------------------------------------------------------------
// mma.sync bf16 hi/lo attention; softmax weights stay in registers as
// A-fragments for GEMM2. Single launch: jid 0..15 -> A16, 16..95 -> A80,
// 96..495 -> raw (writes (4/3)*A400 directly to out; combine adds the rest).
// One CTA = one job. 192 threads = 6 warps; warp w owns M rows [16w,16w+16).
// ---------------------------------------------------------------------------
__global__ void __launch_bounds__(192, 4)
attn_mma(const float* __restrict__ x, const float* __restrict__ cross,
         float* out) {
    extern __shared__ char smem[];
    const uint32_t sb = smem_u32(smem);
    const int tid = threadIdx.x;
    const int w   = tid >> 5;
    const int l   = tid & 31;

    const int jid = blockIdx.x;
    const float *q, *kv;
    float* o;
    int b;
    if (jid < 16)      { q = g_xp16; kv = g_cp16; o = g_A16; b = jid; }
    else if (jid < 96) { q = g_xp80; kv = g_cp80; o = g_A80; b = jid - 16; }
    else               { q = x;      kv = cross;  o = out;   b = jid - 96; }
    const float* qb = q  + (size_t)b * LC;
    const float* kb = kv + (size_t)b * LC;
    float*       ob = o  + (size_t)b * LC;
    const float wscale = (jid >= 96) ? (4.0f / 3.0f) : 1.0f;

    const int m0 = w * 16;
    // ldmatrix lane->address components
    const uint32_t x4off = (uint32_t)((l & 7) + ((l >> 4) & 1) * 8) * QSTR
                         + ((l >> 3) & 1) * 16;                        // K tiles
    const uint32_t aoffQ = (uint32_t)(m0 + (l & 7) + ((l >> 3) & 1) * 8) * QSTR
                         + ((l >> 4) & 1) * 16;
    const uint32_t boffV4 = (uint32_t)((l & 15) * QSTR + ((l >> 4) & 1) * 16);

    // ==== Phase 1: S = Q K^T, K-chunks of 64 channels ========================
    float acc[12][4];
#pragma unroll
    for (int n = 0; n < 12; n++)
#pragma unroll
        for (int u = 0; u < 4; u++) acc[n][u] = 0.f;

    for (int ck = 0; ck < 8; ck++) {
        const int kc = ck * 64;
        __syncthreads();   // prev chunk's mma reads done
#pragma unroll
        for (int i = 0; i < 8; i++) {
            int idx = tid + 192 * i;      // 0..1535 float4 slots
            int row = idx >> 4, c4 = idx & 15;
            uint32_t a = (uint32_t)(row * QSTR + c4 * 8);
            float4 qv = *(const float4*)(qb + row * CH + kc + c4 * 4);
            uint32_t p0h, p0l, p1h, p1l;
            bpack2(qv.x, qv.y, p0h, p0l);
            bpack2(qv.z, qv.w, p1h, p1l);
            STS64V(sb + SM_QHI + a, p0h, p1h);
            STS64V(sb + SM_QLO + a, p0l, p1l);
            float4 kv4 = *(const float4*)(kb + row * CH + kc + c4 * 4);
            bpack2(kv4.x, kv4.y, p0h, p0l);
            bpack2(kv4.z, kv4.w, p1h, p1l);
            STS64V(sb + SM_KHI + a, p0h, p1h);
            STS64V(sb + SM_KLO + a, p0l, p1l);
        }
        __syncthreads();
#pragma unroll
        for (int ks = 0; ks < 4; ks++) {
            const uint32_t kB = (uint32_t)(ks * 32);  // 16 ch = 32 B
            uint32_t ah0,ah1,ah2,ah3, al0,al1,al2,al3;
            LDSM_X4(ah0,ah1,ah2,ah3, sb + SM_QHI + aoffQ + kB);
            LDSM_X4(al0,al1,al2,al3, sb + SM_QLO + aoffQ + kB);
#pragma unroll
            for (int n2 = 0; n2 < 6; n2++) {
                uint32_t ba = sb + SM_KHI + (uint32_t)(n2 * 16 * QSTR) + x4off + kB;
                uint32_t bh0,bh1,bh2,bh3, bl0,bl1,bl2,bl3;
                LDSM_X4(bh0,bh1,bh2,bh3, ba);
                LDSM_X4(bl0,bl1,bl2,bl3, ba + (SM_KLO - SM_KHI));
                mma16816(acc[2*n2],   ah0,ah1,ah2,ah3, bh0,bh1);
                mma16816(acc[2*n2],   ah0,ah1,ah2,ah3, bl0,bl1);
                mma16816(acc[2*n2],   al0,al1,al2,al3, bh0,bh1);
                mma16816(acc[2*n2+1], ah0,ah1,ah2,ah3, bh2,bh3);
                mma16816(acc[2*n2+1], ah0,ah1,ah2,ah3, bl2,bl3);
                mma16816(acc[2*n2+1], al0,al1,al2,al3, bh2,bh3);
            }
        }
    }
    __syncthreads();   // all mma done; smem free for V

    // ==== Phase 2: softmax in registers -> A-fragments in registers ==========
    uint32_t whi[24], wlo[24];
    {
        const float scale = 0.04419417382415922f;  // 1/sqrt(512)
        float mx0 = -3.4e38f, mx1 = -3.4e38f;
#pragma unroll
        for (int n = 0; n < 12; n++) {
#pragma unroll
            for (int u = 0; u < 4; u++) acc[n][u] *= scale;
            mx0 = fmaxf(mx0, fmaxf(acc[n][0], acc[n][1]));
            mx1 = fmaxf(mx1, fmaxf(acc[n][2], acc[n][3]));
        }
        mx0 = fmaxf(mx0, __shfl_xor_sync(0xffffffffu, mx0, 1));
        mx0 = fmaxf(mx0, __shfl_xor_sync(0xffffffffu, mx0, 2));
        mx1 = fmaxf(mx1, __shfl_xor_sync(0xffffffffu, mx1, 1));
        mx1 = fmaxf(mx1, __shfl_xor_sync(0xffffffffu, mx1, 2));
        float s0 = 0.f, s1 = 0.f;
#pragma unroll
        for (int n = 0; n < 12; n++) {
            acc[n][0] = __expf(acc[n][0] - mx0); s0 += acc[n][0];
            acc[n][1] = __expf(acc[n][1] - mx0); s0 += acc[n][1];
            acc[n][2] = __expf(acc[n][2] - mx1); s1 += acc[n][2];
            acc[n][3] = __expf(acc[n][3] - mx1); s1 += acc[n][3];
        }
        s0 += __shfl_xor_sync(0xffffffffu, s0, 1);
        s0 += __shfl_xor_sync(0xffffffffu, s0, 2);
        s1 += __shfl_xor_sync(0xffffffffu, s1, 1);
        s1 += __shfl_xor_sync(0xffffffffu, s1, 2);
        float i0 = wscale / s0, i1 = wscale / s1;   // (4/3 folded for raw jobs)
#pragma unroll
        for (int ks = 0; ks < 6; ks++) {
            bpack2(acc[2*ks][0] * i0,   acc[2*ks][1] * i0,   whi[4*ks+0], wlo[4*ks+0]);
            bpack2(acc[2*ks][2] * i1,   acc[2*ks][3] * i1,   whi[4*ks+1], wlo[4*ks+1]);
            bpack2(acc[2*ks+1][0] * i0, acc[2*ks+1][1] * i0, whi[4*ks+2], wlo[4*ks+2]);
            bpack2(acc[2*ks+1][2] * i1, acc[2*ks+1][3] * i1, whi[4*ks+3], wlo[4*ks+3]);
        }
    }

    // ==== Phase 3: O = W V, double-buffered 64-ch chunks =====================
    // preload chunk 0 -> buf0
    {
#pragma unroll
        for (int i = 0; i < 8; i++) {
            int idx = tid + 192 * i;
            int row = idx >> 4, c4 = idx & 15;
            uint32_t a = (uint32_t)(row * QSTR + c4 * 8);
            float4 vv = *(const float4*)(kb + row * CH + c4 * 4);
            uint32_t p0h, p0l, p1h, p1l;
            bpack2(vv.x, vv.y, p0h, p0l);
            bpack2(vv.z, vv.w, p1h, p1l);
            STS64V(sb + a, p0h, p1h);
            STS64V(sb + 13824u + a, p0l, p1l);
        }
    }
    __syncthreads();

    for (int ci = 0; ci < 8; ci++) {
        const uint32_t bufR = (uint32_t)(ci & 1) * VBUF_STRIDE;
        // stage chunk ci+1 into the other buffer (overlaps this chunk's mma
        // across warps; different buffer so no hazard)
        if (ci < 7) {
            const int cc = (ci + 1) * 64;
            const uint32_t bufW = (uint32_t)((ci + 1) & 1) * VBUF_STRIDE;
#pragma unroll
            for (int i = 0; i < 8; i++) {
                int idx = tid + 192 * i;
                int row = idx >> 4, c4 = idx & 15;
                uint32_t a = (uint32_t)(row * QSTR + c4 * 8);
                float4 vv = *(const float4*)(kb + row * CH + cc + c4 * 4);
                uint32_t p0h, p0l, p1h, p1l;
                bpack2(vv.x, vv.y, p0h, p0l);
                bpack2(vv.z, vv.w, p1h, p1l);
                STS64V(sb + bufW + a, p0h, p1h);
                STS64V(sb + bufW + 13824u + a, p0l, p1l);
            }
        }

        const int cc = ci * 64;
#pragma unroll
        for (int h = 0; h < 2; h++) {
            float acc2[4][4];
#pragma unroll
            for (int n = 0; n < 4; n++)
#pragma unroll
                for (int u = 0; u < 4; u++) acc2[n][u] = 0.f;

#pragma unroll
            for (int ks = 0; ks < 6; ks++) {
                const uint32_t vR = (uint32_t)(ks * 16 * QSTR);
#pragma unroll
                for (int n2 = 0; n2 < 2; n2++) {
                    uint32_t ba = sb + bufR + vR + boffV4
                                + (uint32_t)(h * 64 + n2 * 32);
                    uint32_t bh0,bh1,bh2,bh3, bl0,bl1,bl2,bl3;
                    LDSM_X4T(bh0,bh1,bh2,bh3, ba);
                    LDSM_X4T(bl0,bl1,bl2,bl3, ba + 13824u);
                    mma16816(acc2[2*n2],   whi[4*ks],whi[4*ks+1],whi[4*ks+2],whi[4*ks+3], bh0,bh1);
                    mma16816(acc2[2*n2],   whi[4*ks],whi[4*ks+1],whi[4*ks+2],whi[4*ks+3], bl0,bl1);
                    mma16816(acc2[2*n2],   wlo[4*ks],wlo[4*ks+1],wlo[4*ks+2],wlo[4*ks+3], bh0,bh1);
                    mma16816(acc2[2*n2+1], whi[4*ks],whi[4*ks+1],whi[4*ks+2],whi[4*ks+3], bh2,bh3);
                    mma16816(acc2[2*n2+1], whi[4*ks],whi[4*ks+1],whi[4*ks+2],whi[4*ks+3], bl2,bl3);
                    mma16816(acc2[2*n2+1], wlo[4*ks],wlo[4*ks+1],wlo[4*ks+2],wlo[4*ks+3], bh2,bh3);
                }
            }
            {
                const int g  = l >> 2;
                const int i4 = l & 3;
                const int r0 = m0 + g, r1 = r0 + 8;
#pragma unroll
                for (int n = 0; n < 4; n++) {
                    int col = cc + h * 32 + n * 8 + 2 * i4;
                    *(float2*)(ob + (size_t)r0 * CH + col) = make_float2(acc2[n][0], acc2[n][1]);
                    *(float2*)(ob + (size_t)r1 * CH + col) = make_float2(acc2[n][2], acc2[n][3]);
                }
            }
        }
        __syncthreads();   // buf[ci&1] reads done before it is refilled
    }
}

// ---------------------------------------------------------------------------
// out += (1/3)*(A16[b/25] + A80[b/5])   (out already holds (4/3)*A400)
// 2 float4 per thread for more MLP.
// ---------------------------------------------------------------------------
__global__ void combine(float* __restrict__ out) {
    const int per = LC / 4;
    int t0 = (blockIdx.x * blockDim.x + threadIdx.x) * 2;
    const float c13 = 1.0f / 3.0f;
#pragma unroll
    for (int k = 0; k < 2; k++) {
        int t = t0 + k;
        if (t >= 400 * per) return;
        int b = t / per, m = t - b * per;
        float4 a = ((float4*)out)[t];
        float4 s = ((const float4*)g_A16)[(b / 25) * per + m];
        float4 u = ((const float4*)g_A80)[(b / 5) * per + m];
        a.x += c13 * (s.x + u.x);
        a.y += c13 * (s.y + u.y);
        a.z += c13 * (s.z + u.z);
        a.w += c13 * (s.w + u.w);
        ((float4*)out)[t] = a;
    }
}

// ---------------------------------------------------------------------------
extern "C" void kernel_launch(void* const* d_in, const int* in_sizes, int n_in,
                              void* d_out, int out_size) {
    const float* x     = (const float*)d_in[0];
    const float* cross = (const float*)d_in[1];
    float*       out   = (float*)d_out;

    static bool init_done = false;
    if (!init_done) {
        cudaFuncSetAttribute(attn_mma,
                             cudaFuncAttributeMaxDynamicSharedMemorySize, SMEM_TOTAL);
        init_done = true;
    }

    {
        int total = 80 * (LC / 4);
        pool5_from_input<<<(total + 255) / 256, 256>>>(x, cross);
    }
    {
        int total = 16 * (LC / 4);
        pool5_level2<<<(total + 255) / 256, 256>>>();
    }
    attn_mma<<<496, 192, SMEM_TOTAL>>>(x, cross, out);
    {
        int total = 400 * (LC / 4);          // float4 count
        int threads_needed = (total + 1) / 2;
        combine<<<(threads_needed + 255) / 256, 256>>>(out);
    }
}

// round 15
// speedup vs baseline: 1.2408x; 1.0260x over previous
#include <cuda_runtime.h>
#include <cuda_bf16.h>
#include <cstdint>

#define CH 512
#define LC (96 * 512)      // 49152

// Static device scratch (allocation-free per harness rules).
__device__ float g_xp80[80 * LC];
__device__ float g_cp80[80 * LC];
__device__ float g_xp16[16 * LC];
__device__ float g_cp16[16 * LC];
__device__ float g_A80 [80 * LC];
__device__ float g_A16 [16 * LC];

// ---------------------------------------------------------------------------
// helpers
// ---------------------------------------------------------------------------
__device__ __forceinline__ uint32_t smem_u32(const void* p) {
    uint32_t a;
    asm("{ .reg .u64 t; cvta.to.shared.u64 t, %1; cvt.u32.u64 %0, t; }"
        : "=r"(a) : "l"(p));
    return a;
}

#define LDSM_X4(r0, r1, r2, r3, addr) \
    asm volatile("ldmatrix.sync.aligned.m8n8.x4.shared.b16 {%0,%1,%2,%3}, [%4];" \
                 : "=r"(r0), "=r"(r1), "=r"(r2), "=r"(r3) : "r"(addr))
#define LDSM_X4T(r0, r1, r2, r3, addr) \
    asm volatile("ldmatrix.sync.aligned.m8n8.x4.trans.shared.b16 {%0,%1,%2,%3}, [%4];" \
                 : "=r"(r0), "=r"(r1), "=r"(r2), "=r"(r3) : "r"(addr))

__device__ __forceinline__ void mma16816(float* d, uint32_t a0, uint32_t a1,
                                         uint32_t a2, uint32_t a3,
                                         uint32_t b0, uint32_t b1) {
    asm volatile("mma.sync.aligned.m16n8k16.row.col.f32.bf16.bf16.f32 "
                 "{%0,%1,%2,%3}, {%4,%5,%6,%7}, {%8,%9}, {%0,%1,%2,%3};"
                 : "+f"(d[0]), "+f"(d[1]), "+f"(d[2]), "+f"(d[3])
                 : "r"(a0), "r"(a1), "r"(a2), "r"(a3), "r"(b0), "r"(b1));
}

#define STS64V(addr, a, b) \
    asm volatile("st.shared.v2.b32 [%0], {%1,%2};" :: "r"(addr), "r"(a), "r"(b) : "memory")

// bf16 hi/lo split (scalar)
__device__ __forceinline__ void bsplit(float v, uint32_t& h, uint32_t& l) {
    __nv_bfloat16 hb = __float2bfloat16(v);
    float r = v - __bfloat162float(hb);
    __nv_bfloat16 lb = __float2bfloat16(r);
    h = (uint32_t)__bfloat16_as_ushort(hb);
    l = (uint32_t)__bfloat16_as_ushort(lb);
}
// pack two floats to bf16x2 hi/lo pair (v0 -> low 16 bits)
__device__ __forceinline__ void bpack2(float v0, float v1,
                                       uint32_t& hi, uint32_t& lo) {
    uint32_t h0, l0, h1, l1;
    bsplit(v0, h0, l0); bsplit(v1, h1, l1);
    hi = h0 | (h1 << 16);
    lo = l0 | (l1 << 16);
}

// ---------------------------------------------------------------------------
// 5-way mean pools (two-stage; level-16 derived from level-80 buffer)
// ---------------------------------------------------------------------------
__global__ void pool5_from_input(const float* __restrict__ x,
                                 const float* __restrict__ cr) {
    int t = blockIdx.x * blockDim.x + threadIdx.x;
    const int per = LC / 4;
    if (t >= 80 * per) return;
    int g = t / per, m = t - g * per;
    const float4* xa = (const float4*)x;
    const float4* ca = (const float4*)cr;
    float4 sx = make_float4(0, 0, 0, 0), sc = make_float4(0, 0, 0, 0);
#pragma unroll
    for (int j = 0; j < 5; j++) {
        float4 a = xa[(g * 5 + j) * per + m], b = ca[(g * 5 + j) * per + m];
        sx.x += a.x; sx.y += a.y; sx.z += a.z; sx.w += a.w;
        sc.x += b.x; sc.y += b.y; sc.z += b.z; sc.w += b.w;
    }
    const float s = 0.2f;
    sx.x *= s; sx.y *= s; sx.z *= s; sx.w *= s;
    sc.x *= s; sc.y *= s; sc.z *= s; sc.w *= s;
    ((float4*)g_xp80)[g * per + m] = sx;
    ((float4*)g_cp80)[g * per + m] = sc;
}

__global__ void pool5_level2() {
    int t = blockIdx.x * blockDim.x + threadIdx.x;
    const int per = LC / 4;
    if (t >= 16 * per) return;
    int g = t / per, m = t - g * per;
    const float4* xa = (const float4*)g_xp80;
    const float4* ca = (const float4*)g_cp80;
    float4 sx = make_float4(0, 0, 0, 0), sc = make_float4(0, 0, 0, 0);
#pragma unroll
    for (int j = 0; j < 5; j++) {
        float4 a = xa[(g * 5 + j) * per + m], b = ca[(g * 5 + j) * per + m];
        sx.x += a.x; sx.y += a.y; sx.z += a.z; sx.w += a.w;
        sc.x += b.x; sc.y += b.y; sc.z += b.z; sc.w += b.w;
    }
    const float s = 0.2f;
    sx.x *= s; sx.y *= s; sx.z *= s; sx.w *= s;
    sc.x *= s; sc.y *= s; sc.z *= s; sc.w *= s;
    ((float4*)g_xp16)[g * per + m] = sx;
    ((float4*)g_cp16)[g * per + m] = sc;
}

// ---------------------------------------------------------------------------
// Smem layout (bytes).
// Phase 1 (single-buffered, 64-ch chunks): QHI/QLO/KHI/KLO, 96 rows x 144 B
//   stride (multiple of 16 for ldmatrix alignment), 4 x 13824 = 55296.
// Phase 3 (double-buffered, 64-ch chunks): buf k at k*27648; VHI +0, VLO +13824;
//   tile = 96 rows x 144 B stride.
// Total 55296 -> 4 CTAs/SM.
// ---------------------------------------------------------------------------
#define QSTR 144
#define SM_QHI 0u
#define SM_QLO 13824u
#define SM_KHI 27648u
#define SM_KLO 41472u      // end: 55296
#define VBUF_STRIDE 27648u // buf k at k*27648; HI at +0, LO at +13824
#define SMEM_TOTAL 55296

// ---------------------------------------------------------------------------
// mma.sync bf16 hi/lo attention; softmax weights stay in registers as
// A-fragments for GEMM2. jid = blockIdx.x + jbase:
//   0..15 -> A16, 16..95 -> A80, 96..495 -> raw ((4/3)*A400 direct to out).
// One CTA = one job. 192 threads = 6 warps; warp w owns M rows [16w,16w+16).
// ---------------------------------------------------------------------------
__global__ void __launch_bounds__(192, 4)
attn_mma(const float* __restrict__ x, const float* __restrict__ cross,
         float* out, int jbase) {
    extern __shared__ char smem[];
    const uint32_t sb = smem_u32(smem);
    const int tid = threadIdx.x;
    const int w   = tid >> 5;
    const int l   = tid & 31;

    const int jid = blockIdx.x + jbase;
    const float *q, *kv;
    float* o;
    int b;
    if (jid < 16)      { q = g_xp16; kv = g_cp16; o = g_A16; b = jid; }
    else if (jid < 96) { q = g_xp80; kv = g_cp80; o = g_A80; b = jid - 16; }
    else               { q = x;      kv = cross;  o = out;   b = jid - 96; }
    const float* qb = q  + (size_t)b * LC;
    const float* kb = kv + (size_t)b * LC;
    float*       ob = o  + (size_t)b * LC;
    const float wscale = (jid >= 96) ? (4.0f / 3.0f) : 1.0f;

    const int m0 = w * 16;
    // ldmatrix lane->address components
    const uint32_t x4off = (uint32_t)((l & 7) + ((l >> 4) & 1) * 8) * QSTR
                         + ((l >> 3) & 1) * 16;                        // K tiles
    const uint32_t aoffQ = (uint32_t)(m0 + (l & 7) + ((l >> 3) & 1) * 8) * QSTR
                         + ((l >> 4) & 1) * 16;
    const uint32_t boffV4 = (uint32_t)((l & 15) * QSTR + ((l >> 4) & 1) * 16);

    // ==== Phase 1: S = Q K^T, K-chunks of 64 channels ========================
    float acc[12][4];
#pragma unroll
    for (int n = 0; n < 12; n++)
#pragma unroll
        for (int u = 0; u < 4; u++) acc[n][u] = 0.f;

    for (int ck = 0; ck < 8; ck++) {
        const int kc = ck * 64;
        __syncthreads();   // prev chunk's mma reads done
#pragma unroll
        for (int i = 0; i < 8; i++) {
            int idx = tid + 192 * i;      // 0..1535 float4 slots
            int row = idx >> 4, c4 = idx & 15;
            uint32_t a = (uint32_t)(row * QSTR + c4 * 8);
            float4 qv = *(const float4*)(qb + row * CH + kc + c4 * 4);
            uint32_t p0h, p0l, p1h, p1l;
            bpack2(qv.x, qv.y, p0h, p0l);
            bpack2(qv.z, qv.w, p1h, p1l);
            STS64V(sb + SM_QHI + a, p0h, p1h);
            STS64V(sb + SM_QLO + a, p0l, p1l);
            float4 kv4 = *(const float4*)(kb + row * CH + kc + c4 * 4);
            bpack2(kv4.x, kv4.y, p0h, p0l);
            bpack2(kv4.z, kv4.w, p1h, p1l);
            STS64V(sb + SM_KHI + a, p0h, p1h);
            STS64V(sb + SM_KLO + a, p0l, p1l);
        }
        __syncthreads();
#pragma unroll
        for (int ks = 0; ks < 4; ks++) {
            const uint32_t kB = (uint32_t)(ks * 32);  // 16 ch = 32 B
            uint32_t ah0,ah1,ah2,ah3, al0,al1,al2,al3;
            LDSM_X4(ah0,ah1,ah2,ah3, sb + SM_QHI + aoffQ + kB);
            LDSM_X4(al0,al1,al2,al3, sb + SM_QLO + aoffQ + kB);
#pragma unroll
            for (int n2 = 0; n2 < 6; n2++) {
                uint32_t ba = sb + SM_KHI + (uint32_t)(n2 * 16 * QSTR) + x4off + kB;
                uint32_t bh0,bh1,bh2,bh3, bl0,bl1,bl2,bl3;
                LDSM_X4(bh0,bh1,bh2,bh3, ba);
                LDSM_X4(bl0,bl1,bl2,bl3, ba + (SM_KLO - SM_KHI));
                mma16816(acc[2*n2],   ah0,ah1,ah2,ah3, bh0,bh1);
                mma16816(acc[2*n2],   ah0,ah1,ah2,ah3, bl0,bl1);
                mma16816(acc[2*n2],   al0,al1,al2,al3, bh0,bh1);
                mma16816(acc[2*n2+1], ah0,ah1,ah2,ah3, bh2,bh3);
                mma16816(acc[2*n2+1], ah0,ah1,ah2,ah3, bl2,bl3);
                mma16816(acc[2*n2+1], al0,al1,al2,al3, bh2,bh3);
            }
        }
    }
    __syncthreads();   // all mma done; smem free for V

    // ==== Phase 2: softmax in registers -> A-fragments in registers ==========
    uint32_t whi[24], wlo[24];
    {
        const float scale = 0.04419417382415922f;  // 1/sqrt(512)
        float mx0 = -3.4e38f, mx1 = -3.4e38f;
#pragma unroll
        for (int n = 0; n < 12; n++) {
#pragma unroll
            for (int u = 0; u < 4; u++) acc[n][u] *= scale;
            mx0 = fmaxf(mx0, fmaxf(acc[n][0], acc[n][1]));
            mx1 = fmaxf(mx1, fmaxf(acc[n][2], acc[n][3]));
        }
        mx0 = fmaxf(mx0, __shfl_xor_sync(0xffffffffu, mx0, 1));
        mx0 = fmaxf(mx0, __shfl_xor_sync(0xffffffffu, mx0, 2));
        mx1 = fmaxf(mx1, __shfl_xor_sync(0xffffffffu, mx1, 1));
        mx1 = fmaxf(mx1, __shfl_xor_sync(0xffffffffu, mx1, 2));
        float s0 = 0.f, s1 = 0.f;
#pragma unroll
        for (int n = 0; n < 12; n++) {
            acc[n][0] = __expf(acc[n][0] - mx0); s0 += acc[n][0];
            acc[n][1] = __expf(acc[n][1] - mx0); s0 += acc[n][1];
            acc[n][2] = __expf(acc[n][2] - mx1); s1 += acc[n][2];
            acc[n][3] = __expf(acc[n][3] - mx1); s1 += acc[n][3];
        }
        s0 += __shfl_xor_sync(0xffffffffu, s0, 1);
        s0 += __shfl_xor_sync(0xffffffffu, s0, 2);
        s1 += __shfl_xor_sync(0xffffffffu, s1, 1);
        s1 += __shfl_xor_sync(0xffffffffu, s1, 2);
        float i0 = wscale / s0, i1 = wscale / s1;   // (4/3 folded for raw jobs)
#pragma unroll
        for (int ks = 0; ks < 6; ks++) {
            bpack2(acc[2*ks][0] * i0,   acc[2*ks][1] * i0,   whi[4*ks+0], wlo[4*ks+0]);
            bpack2(acc[2*ks][2] * i1,   acc[2*ks][3] * i1,   whi[4*ks+1], wlo[4*ks+1]);
            bpack2(acc[2*ks+1][0] * i0, acc[2*ks+1][1] * i0, whi[4*ks+2], wlo[4*ks+2]);
            bpack2(acc[2*ks+1][2] * i1, acc[2*ks+1][3] * i1, whi[4*ks+3], wlo[4*ks+3]);
        }
    }

    // ==== Phase 3: O = W V, double-buffered 64-ch chunks =====================
    auto stage3 = [&](int ci, uint32_t buf) {
        const int cc = ci * 64;
#pragma unroll
        for (int i = 0; i < 8; i++) {
            int idx = tid + 192 * i;
            int row = idx >> 4, c4 = idx & 15;
            uint32_t a = buf + (uint32_t)(row * QSTR + c4 * 8);
            float4 vv = *(const float4*)(kb + row * CH + cc + c4 * 4);
            uint32_t p0h, p0l, p1h, p1l;
            bpack2(vv.x, vv.y, p0h, p0l);
            bpack2(vv.z, vv.w, p1h, p1l);
            STS64V(sb + a, p0h, p1h);
            STS64V(sb + 13824u + a, p0l, p1l);
        }
    };

    stage3(0, 0u);
    __syncthreads();

    for (int ci = 0; ci < 8; ci++) {
        const uint32_t bufR = (uint32_t)(ci & 1) * VBUF_STRIDE;
        // stage chunk ci+1 into the other buffer (overlaps this chunk's mma
        // across warps; different buffer so no hazard)
        if (ci < 7) stage3(ci + 1, (uint32_t)((ci + 1) & 1) * VBUF_STRIDE);

        const int cc = ci * 64;
#pragma unroll
        for (int h = 0; h < 2; h++) {
            float acc2[4][4];
#pragma unroll
            for (int n = 0; n < 4; n++)
#pragma unroll
                for (int u = 0; u < 4; u++) acc2[n][u] = 0.f;

#pragma unroll
            for (int ks = 0; ks < 6; ks++) {
                const uint32_t vR = (uint32_t)(ks * 16 * QSTR);
#pragma unroll
                for (int n2 = 0; n2 < 2; n2++) {
                    uint32_t ba = sb + bufR + vR + boffV4
                                + (uint32_t)(h * 64 + n2 * 32);
                    uint32_t bh0,bh1,bh2,bh3, bl0,bl1,bl2,bl3;
                    LDSM_X4T(bh0,bh1,bh2,bh3, ba);
                    LDSM_X4T(bl0,bl1,bl2,bl3, ba + 13824u);
                    mma16816(acc2[2*n2],   whi[4*ks],whi[4*ks+1],whi[4*ks+2],whi[4*ks+3], bh0,bh1);
                    mma16816(acc2[2*n2],   whi[4*ks],whi[4*ks+1],whi[4*ks+2],whi[4*ks+3], bl0,bl1);
                    mma16816(acc2[2*n2],   wlo[4*ks],wlo[4*ks+1],wlo[4*ks+2],wlo[4*ks+3], bh0,bh1);
                    mma16816(acc2[2*n2+1], whi[4*ks],whi[4*ks+1],whi[4*ks+2],whi[4*ks+3], bh2,bh3);
                    mma16816(acc2[2*n2+1], whi[4*ks],whi[4*ks+1],whi[4*ks+2],whi[4*ks+3], bl2,bl3);
                    mma16816(acc2[2*n2+1], wlo[4*ks],wlo[4*ks+1],wlo[4*ks+2],wlo[4*ks+3], bh2,bh3);
                }
            }
            {
                const int g  = l >> 2;
                const int i4 = l & 3;
                const int r0 = m0 + g, r1 = r0 + 8;
#pragma unroll
                for (int n = 0; n < 4; n++) {
                    int col = cc + h * 32 + n * 8 + 2 * i4;
                    *(float2*)(ob + (size_t)r0 * CH + col) = make_float2(acc2[n][0], acc2[n][1]);
                    *(float2*)(ob + (size_t)r1 * CH + col) = make_float2(acc2[n][2], acc2[n][3]);
                }
            }
        }
        __syncthreads();   // buf[ci&1] reads done before it is refilled
    }
}

// ---------------------------------------------------------------------------
// out += (1/3)*(A16[b/25] + A80[b/5])   (out already holds (4/3)*A400)
// ---------------------------------------------------------------------------
__global__ void combine(float* __restrict__ out) {
    int t = blockIdx.x * blockDim.x + threadIdx.x;
    const int per = LC / 4;
    if (t >= 400 * per) return;
    int b = t / per, m = t - b * per;
    const float c13 = 1.0f / 3.0f;
    float4 a = ((float4*)out)[t];
    float4 s = ((const float4*)g_A16)[(b / 25) * per + m];
    float4 u = ((const float4*)g_A80)[(b / 5) * per + m];
    a.x += c13 * (s.x + u.x);
    a.y += c13 * (s.y + u.y);
    a.z += c13 * (s.z + u.z);
    a.w += c13 * (s.w + u.w);
    ((float4*)out)[t] = a;
}

// ---------------------------------------------------------------------------
extern "C" void kernel_launch(void* const* d_in, const int* in_sizes, int n_in,
                              void* d_out, int out_size) {
    const float* x     = (const float*)d_in[0];
    const float* cross = (const float*)d_in[1];
    float*       out   = (float*)d_out;

    static bool init_done = false;
    static cudaStream_t s2;
    static cudaEvent_t e0, e1;
    if (!init_done) {
        cudaFuncSetAttribute(attn_mma,
                             cudaFuncAttributeMaxDynamicSharedMemorySize, SMEM_TOTAL);
        cudaStreamCreateWithFlags(&s2, cudaStreamNonBlocking);
        cudaEventCreateWithFlags(&e0, cudaEventDisableTiming);
        cudaEventCreateWithFlags(&e1, cudaEventDisableTiming);
        init_done = true;
    }

    // Fork: side stream runs pools -> 96 pooled jobs (fits in the 192 CTA
    // slots the 400-CTA raw launch leaves free at 4 CTAs/SM); main stream
    // runs the 400 raw jobs concurrently. Join, then combine.
    cudaEventRecord(e0, 0);
    cudaStreamWaitEvent(s2, e0, 0);

    {
        int total = 80 * (LC / 4);
        pool5_from_input<<<(total + 255) / 256, 256, 0, s2>>>(x, cross);
    }
    {
        int total = 16 * (LC / 4);
        pool5_level2<<<(total + 255) / 256, 256, 0, s2>>>();
    }
    attn_mma<<<96, 192, SMEM_TOTAL, s2>>>(x, cross, out, 0);   // pooled jobs
    cudaEventRecord(e1, s2);

    attn_mma<<<400, 192, SMEM_TOTAL>>>(x, cross, out, 96);     // raw jobs

    cudaStreamWaitEvent(0, e1, 0);
    {
        int total = 400 * (LC / 4);
        combine<<<(total + 255) / 256, 256>>>(out);
    }
}

// round 17
// speedup vs baseline: 1.2985x; 1.0465x over previous
#include <cuda_runtime.h>
#include <cuda_bf16.h>
#include <cstdint>

#define CH 512
#define LC (96 * 512)      // 49152

// Static device scratch (allocation-free per harness rules).
__device__ float g_xp80[80 * LC];
__device__ float g_cp80[80 * LC];
__device__ float g_xp16[16 * LC];
__device__ float g_cp16[16 * LC];
__device__ float g_A80 [80 * LC];
__device__ float g_A16 [16 * LC];

// ---------------------------------------------------------------------------
// helpers
// ---------------------------------------------------------------------------
__device__ __forceinline__ uint32_t smem_u32(const void* p) {
    uint32_t a;
    asm("{ .reg .u64 t; cvta.to.shared.u64 t, %1; cvt.u32.u64 %0, t; }"
        : "=r"(a) : "l"(p));
    return a;
}

#define LDSM_X4(r0, r1, r2, r3, addr) \
    asm volatile("ldmatrix.sync.aligned.m8n8.x4.shared.b16 {%0,%1,%2,%3}, [%4];" \
                 : "=r"(r0), "=r"(r1), "=r"(r2), "=r"(r3) : "r"(addr))
#define LDSM_X4T(r0, r1, r2, r3, addr) \
    asm volatile("ldmatrix.sync.aligned.m8n8.x4.trans.shared.b16 {%0,%1,%2,%3}, [%4];" \
                 : "=r"(r0), "=r"(r1), "=r"(r2), "=r"(r3) : "r"(addr))

__device__ __forceinline__ void mma16816(float* d, uint32_t a0, uint32_t a1,
                                         uint32_t a2, uint32_t a3,
                                         uint32_t b0, uint32_t b1) {
    asm volatile("mma.sync.aligned.m16n8k16.row.col.f32.bf16.bf16.f32 "
                 "{%0,%1,%2,%3}, {%4,%5,%6,%7}, {%8,%9}, {%0,%1,%2,%3};"
                 : "+f"(d[0]), "+f"(d[1]), "+f"(d[2]), "+f"(d[3])
                 : "r"(a0), "r"(a1), "r"(a2), "r"(a3), "r"(b0), "r"(b1));
}

#define STS64V(addr, a, b) \
    asm volatile("st.shared.v2.b32 [%0], {%1,%2};" :: "r"(addr), "r"(a), "r"(b) : "memory")

// Fast bf16 hi/lo split of two floats:
//   hi = truncated top-16 bits of each (1 PRMT for the packed pair),
//   lo = rn(v - hi) (2 LOP3-mask + 2 FSUB + 1 packed cvt).
// Truncation doubles |lo| vs round-nearest; dropped lo*lo term stays ~2^-16.
__device__ __forceinline__ void bpack2(float v0, float v1,
                                       uint32_t& hi, uint32_t& lo) {
    uint32_t u0 = __float_as_uint(v0), u1 = __float_as_uint(v1);
    uint32_t h;
    asm("prmt.b32 %0, %1, %2, 0x7632;" : "=r"(h) : "r"(u0), "r"(u1));
    float r0 = v0 - __uint_as_float(u0 & 0xFFFF0000u);
    float r1 = v1 - __uint_as_float(u1 & 0xFFFF0000u);
    uint32_t l2;
    asm("cvt.rn.bf16x2.f32 %0, %1, %2;" : "=r"(l2) : "f"(r1), "f"(r0));
    hi = h;
    lo = l2;
}

// ---------------------------------------------------------------------------
// 5-way mean pools (two-stage; level-16 derived from level-80 buffer)
// ---------------------------------------------------------------------------
__global__ void pool5_from_input(const float* __restrict__ x,
                                 const float* __restrict__ cr) {
    int t = blockIdx.x * blockDim.x + threadIdx.x;
    const int per = LC / 4;
    if (t >= 80 * per) return;
    int g = t / per, m = t - g * per;
    const float4* xa = (const float4*)x;
    const float4* ca = (const float4*)cr;
    float4 sx = make_float4(0, 0, 0, 0), sc = make_float4(0, 0, 0, 0);
#pragma unroll
    for (int j = 0; j < 5; j++) {
        float4 a = xa[(g * 5 + j) * per + m], b = ca[(g * 5 + j) * per + m];
        sx.x += a.x; sx.y += a.y; sx.z += a.z; sx.w += a.w;
        sc.x += b.x; sc.y += b.y; sc.z += b.z; sc.w += b.w;
    }
    const float s = 0.2f;
    sx.x *= s; sx.y *= s; sx.z *= s; sx.w *= s;
    sc.x *= s; sc.y *= s; sc.z *= s; sc.w *= s;
    ((float4*)g_xp80)[g * per + m] = sx;
    ((float4*)g_cp80)[g * per + m] = sc;
}

__global__ void pool5_level2() {
    int t = blockIdx.x * blockDim.x + threadIdx.x;
    const int per = LC / 4;
    if (t >= 16 * per) return;
    int g = t / per, m = t - g * per;
    const float4* xa = (const float4*)g_xp80;
    const float4* ca = (const float4*)g_cp80;
    float4 sx = make_float4(0, 0, 0, 0), sc = make_float4(0, 0, 0, 0);
#pragma unroll
    for (int j = 0; j < 5; j++) {
        float4 a = xa[(g * 5 + j) * per + m], b = ca[(g * 5 + j) * per + m];
        sx.x += a.x; sx.y += a.y; sx.z += a.z; sx.w += a.w;
        sc.x += b.x; sc.y += b.y; sc.z += b.z; sc.w += b.w;
    }
    const float s = 0.2f;
    sx.x *= s; sx.y *= s; sx.z *= s; sx.w *= s;
    sc.x *= s; sc.y *= s; sc.z *= s; sc.w *= s;
    ((float4*)g_xp16)[g * per + m] = sx;
    ((float4*)g_cp16)[g * per + m] = sc;
}

// ---------------------------------------------------------------------------
// Smem layout (bytes).
// Phase 1 (single-buffered, 64-ch chunks): QHI/QLO/KHI/KLO, 96 rows x 144 B
//   stride (multiple of 16 for ldmatrix alignment), 4 x 13824 = 55296.
// Phase 3 (double-buffered, 64-ch chunks): buf k at k*27648; VHI +0, VLO +13824;
//   tile = 96 rows x 144 B stride.
// Total 55296 -> 4 CTAs/SM.
// ---------------------------------------------------------------------------
#define QSTR 144
#define SM_QHI 0u
#define SM_QLO 13824u
#define SM_KHI 27648u
#define SM_KLO 41472u      // end: 55296
#define VBUF_STRIDE 27648u // buf k at k*27648; HI at +0, LO at +13824
#define SMEM_TOTAL 55296

// ---------------------------------------------------------------------------
// mma.sync bf16 hi/lo attention; softmax weights stay in registers as
// A-fragments for GEMM2. jid = blockIdx.x + jbase:
//   0..15 -> A16, 16..95 -> A80, 96..495 -> raw ((4/3)*A400 direct to out).
// One CTA = one job. 192 threads = 6 warps; warp w owns M rows [16w,16w+16).
// ---------------------------------------------------------------------------
__global__ void __launch_bounds__(192, 4)
attn_mma(const float* __restrict__ x, const float* __restrict__ cross,
         float* out, int jbase) {
    extern __shared__ char smem[];
    const uint32_t sb = smem_u32(smem);
    const int tid = threadIdx.x;
    const int w   = tid >> 5;
    const int l   = tid & 31;

    const int jid = blockIdx.x + jbase;
    const float *q, *kv;
    float* o;
    int b;
    if (jid < 16)      { q = g_xp16; kv = g_cp16; o = g_A16; b = jid; }
    else if (jid < 96) { q = g_xp80; kv = g_cp80; o = g_A80; b = jid - 16; }
    else               { q = x;      kv = cross;  o = out;   b = jid - 96; }
    const float* qb = q  + (size_t)b * LC;
    const float* kb = kv + (size_t)b * LC;
    float*       ob = o  + (size_t)b * LC;
    const float wscale = (jid >= 96) ? (4.0f / 3.0f) : 1.0f;

    const int m0 = w * 16;
    // ldmatrix lane->address components
    const uint32_t x4off = (uint32_t)((l & 7) + ((l >> 4) & 1) * 8) * QSTR
                         + ((l >> 3) & 1) * 16;                        // K tiles
    const uint32_t aoffQ = (uint32_t)(m0 + (l & 7) + ((l >> 3) & 1) * 8) * QSTR
                         + ((l >> 4) & 1) * 16;
    const uint32_t boffV4 = (uint32_t)((l & 15) * QSTR + ((l >> 4) & 1) * 16);

    // ==== Phase 1: S = Q K^T, K-chunks of 64 channels ========================
    float acc[12][4];
#pragma unroll
    for (int n = 0; n < 12; n++)
#pragma unroll
        for (int u = 0; u < 4; u++) acc[n][u] = 0.f;

    for (int ck = 0; ck < 8; ck++) {
        const int kc = ck * 64;
        __syncthreads();   // prev chunk's mma reads done
#pragma unroll
        for (int i = 0; i < 8; i++) {
            int idx = tid + 192 * i;      // 0..1535 float4 slots
            int row = idx >> 4, c4 = idx & 15;
            uint32_t a = (uint32_t)(row * QSTR + c4 * 8);
            float4 qv = *(const float4*)(qb + row * CH + kc + c4 * 4);
            uint32_t p0h, p0l, p1h, p1l;
            bpack2(qv.x, qv.y, p0h, p0l);
            bpack2(qv.z, qv.w, p1h, p1l);
            STS64V(sb + SM_QHI + a, p0h, p1h);
            STS64V(sb + SM_QLO + a, p0l, p1l);
            float4 kv4 = *(const float4*)(kb + row * CH + kc + c4 * 4);
            bpack2(kv4.x, kv4.y, p0h, p0l);
            bpack2(kv4.z, kv4.w, p1h, p1l);
            STS64V(sb + SM_KHI + a, p0h, p1h);
            STS64V(sb + SM_KLO + a, p0l, p1l);
        }
        __syncthreads();
#pragma unroll
        for (int ks = 0; ks < 4; ks++) {
            const uint32_t kB = (uint32_t)(ks * 32);  // 16 ch = 32 B
            uint32_t ah0,ah1,ah2,ah3, al0,al1,al2,al3;
            LDSM_X4(ah0,ah1,ah2,ah3, sb + SM_QHI + aoffQ + kB);
            LDSM_X4(al0,al1,al2,al3, sb + SM_QLO + aoffQ + kB);
#pragma unroll
            for (int n2 = 0; n2 < 6; n2++) {
                uint32_t ba = sb + SM_KHI + (uint32_t)(n2 * 16 * QSTR) + x4off + kB;
                uint32_t bh0,bh1,bh2,bh3, bl0,bl1,bl2,bl3;
                LDSM_X4(bh0,bh1,bh2,bh3, ba);
                LDSM_X4(bl0,bl1,bl2,bl3, ba + (SM_KLO - SM_KHI));
                mma16816(acc[2*n2],   ah0,ah1,ah2,ah3, bh0,bh1);
                mma16816(acc[2*n2],   ah0,ah1,ah2,ah3, bl0,bl1);
                mma16816(acc[2*n2],   al0,al1,al2,al3, bh0,bh1);
                mma16816(acc[2*n2+1], ah0,ah1,ah2,ah3, bh2,bh3);
                mma16816(acc[2*n2+1], ah0,ah1,ah2,ah3, bl2,bl3);
                mma16816(acc[2*n2+1], al0,al1,al2,al3, bh2,bh3);
            }
        }
    }
    __syncthreads();   // all mma done; smem free for V

    // ==== Phase 2: softmax in registers -> A-fragments in registers ==========
    uint32_t whi[24], wlo[24];
    {
        const float scale = 0.04419417382415922f;  // 1/sqrt(512)
        float mx0 = -3.4e38f, mx1 = -3.4e38f;
#pragma unroll
        for (int n = 0; n < 12; n++) {
#pragma unroll
            for (int u = 0; u < 4; u++) acc[n][u] *= scale;
            mx0 = fmaxf(mx0, fmaxf(acc[n][0], acc[n][1]));
            mx1 = fmaxf(mx1, fmaxf(acc[n][2], acc[n][3]));
        }
        mx0 = fmaxf(mx0, __shfl_xor_sync(0xffffffffu, mx0, 1));
        mx0 = fmaxf(mx0, __shfl_xor_sync(0xffffffffu, mx0, 2));
        mx1 = fmaxf(mx1, __shfl_xor_sync(0xffffffffu, mx1, 1));
        mx1 = fmaxf(mx1, __shfl_xor_sync(0xffffffffu, mx1, 2));
        float s0 = 0.f, s1 = 0.f;
#pragma unroll
        for (int n = 0; n < 12; n++) {
            acc[n][0] = __expf(acc[n][0] - mx0); s0 += acc[n][0];
            acc[n][1] = __expf(acc[n][1] - mx0); s0 += acc[n][1];
            acc[n][2] = __expf(acc[n][2] - mx1); s1 += acc[n][2];
            acc[n][3] = __expf(acc[n][3] - mx1); s1 += acc[n][3];
        }
        s0 += __shfl_xor_sync(0xffffffffu, s0, 1);
        s0 += __shfl_xor_sync(0xffffffffu, s0, 2);
        s1 += __shfl_xor_sync(0xffffffffu, s1, 1);
        s1 += __shfl_xor_sync(0xffffffffu, s1, 2);
        float i0 = wscale / s0, i1 = wscale / s1;   // (4/3 folded for raw jobs)
#pragma unroll
        for (int ks = 0; ks < 6; ks++) {
            bpack2(acc[2*ks][0] * i0,   acc[2*ks][1] * i0,   whi[4*ks+0], wlo[4*ks+0]);
            bpack2(acc[2*ks][2] * i1,   acc[2*ks][3] * i1,   whi[4*ks+1], wlo[4*ks+1]);
            bpack2(acc[2*ks+1][0] * i0, acc[2*ks+1][1] * i0, whi[4*ks+2], wlo[4*ks+2]);
            bpack2(acc[2*ks+1][2] * i1, acc[2*ks+1][3] * i1, whi[4*ks+3], wlo[4*ks+3]);
        }
    }

    // ==== Phase 3: O = W V, double-buffered 64-ch chunks =====================
    auto stage3 = [&](int ci, uint32_t buf) {
        const int cc = ci * 64;
#pragma unroll
        for (int i = 0; i < 8; i++) {
            int idx = tid + 192 * i;
            int row = idx >> 4, c4 = idx & 15;
            uint32_t a = buf + (uint32_t)(row * QSTR + c4 * 8);
            float4 vv = *(const float4*)(kb + row * CH + cc + c4 * 4);
            uint32_t p0h, p0l, p1h, p1l;
            bpack2(vv.x, vv.y, p0h, p0l);
            bpack2(vv.z, vv.w, p1h, p1l);
            STS64V(sb + a, p0h, p1h);
            STS64V(sb + 13824u + a, p0l, p1l);
        }
    };

    stage3(0, 0u);
    __syncthreads();

    for (int ci = 0; ci < 8; ci++) {
        const uint32_t bufR = (uint32_t)(ci & 1) * VBUF_STRIDE;
        // stage chunk ci+1 into the other buffer (overlaps this chunk's mma
        // across warps; different buffer so no hazard)
        if (ci < 7) stage3(ci + 1, (uint32_t)((ci + 1) & 1) * VBUF_STRIDE);

        const int cc = ci * 64;
#pragma unroll
        for (int h = 0; h < 2; h++) {
            float acc2[4][4];
#pragma unroll
            for (int n = 0; n < 4; n++)
#pragma unroll
                for (int u = 0; u < 4; u++) acc2[n][u] = 0.f;

#pragma unroll
            for (int ks = 0; ks < 6; ks++) {
                const uint32_t vR = (uint32_t)(ks * 16 * QSTR);
#pragma unroll
                for (int n2 = 0; n2 < 2; n2++) {
                    uint32_t ba = sb + bufR + vR + boffV4
                                + (uint32_t)(h * 64 + n2 * 32);
                    uint32_t bh0,bh1,bh2,bh3, bl0,bl1,bl2,bl3;
                    LDSM_X4T(bh0,bh1,bh2,bh3, ba);
                    LDSM_X4T(bl0,bl1,bl2,bl3, ba + 13824u);
                    mma16816(acc2[2*n2],   whi[4*ks],whi[4*ks+1],whi[4*ks+2],whi[4*ks+3], bh0,bh1);
                    mma16816(acc2[2*n2],   whi[4*ks],whi[4*ks+1],whi[4*ks+2],whi[4*ks+3], bl0,bl1);
                    mma16816(acc2[2*n2],   wlo[4*ks],wlo[4*ks+1],wlo[4*ks+2],wlo[4*ks+3], bh0,bh1);
                    mma16816(acc2[2*n2+1], whi[4*ks],whi[4*ks+1],whi[4*ks+2],whi[4*ks+3], bh2,bh3);
                    mma16816(acc2[2*n2+1], whi[4*ks],whi[4*ks+1],whi[4*ks+2],whi[4*ks+3], bl2,bl3);
                    mma16816(acc2[2*n2+1], wlo[4*ks],wlo[4*ks+1],wlo[4*ks+2],wlo[4*ks+3], bh2,bh3);
                }
            }
            {
                const int g  = l >> 2;
                const int i4 = l & 3;
                const int r0 = m0 + g, r1 = r0 + 8;
#pragma unroll
                for (int n = 0; n < 4; n++) {
                    int col = cc + h * 32 + n * 8 + 2 * i4;
                    *(float2*)(ob + (size_t)r0 * CH + col) = make_float2(acc2[n][0], acc2[n][1]);
                    *(float2*)(ob + (size_t)r1 * CH + col) = make_float2(acc2[n][2], acc2[n][3]);
                }
            }
        }
        __syncthreads();   // buf[ci&1] reads done before it is refilled
    }
}

// ---------------------------------------------------------------------------
// out += (1/3)*(A16[b/25] + A80[b/5])   (out already holds (4/3)*A400)
// ---------------------------------------------------------------------------
__global__ void combine(float* __restrict__ out) {
    int t = blockIdx.x * blockDim.x + threadIdx.x;
    const int per = LC / 4;
    if (t >= 400 * per) return;
    int b = t / per, m = t - b * per;
    const float c13 = 1.0f / 3.0f;
    float4 a = ((float4*)out)[t];
    float4 s = ((const float4*)g_A16)[(b / 25) * per + m];
    float4 u = ((const float4*)g_A80)[(b / 5) * per + m];
    a.x += c13 * (s.x + u.x);
    a.y += c13 * (s.y + u.y);
    a.z += c13 * (s.z + u.z);
    a.w += c13 * (s.w + u.w);
    ((float4*)out)[t] = a;
}

// ---------------------------------------------------------------------------
extern "C" void kernel_launch(void* const* d_in, const int* in_sizes, int n_in,
                              void* d_out, int out_size) {
    const float* x     = (const float*)d_in[0];
    const float* cross = (const float*)d_in[1];
    float*       out   = (float*)d_out;

    static bool init_done = false;
    static cudaStream_t s2;
    static cudaEvent_t e0, e1;
    if (!init_done) {
        cudaFuncSetAttribute(attn_mma,
                             cudaFuncAttributeMaxDynamicSharedMemorySize, SMEM_TOTAL);
        cudaStreamCreateWithFlags(&s2, cudaStreamNonBlocking);
        cudaEventCreateWithFlags(&e0, cudaEventDisableTiming);
        cudaEventCreateWithFlags(&e1, cudaEventDisableTiming);
        init_done = true;
    }

    // Fork: side stream runs pools -> 96 pooled jobs (fits in the 192 CTA
    // slots the 400-CTA raw launch leaves free at 4 CTAs/SM); main stream
    // runs the 400 raw jobs concurrently. Join, then combine.
    cudaEventRecord(e0, 0);
    cudaStreamWaitEvent(s2, e0, 0);

    {
        int total = 80 * (LC / 4);
        pool5_from_input<<<(total + 255) / 256, 256, 0, s2>>>(x, cross);
    }
    {
        int total = 16 * (LC / 4);
        pool5_level2<<<(total + 255) / 256, 256, 0, s2>>>();
    }
    attn_mma<<<96, 192, SMEM_TOTAL, s2>>>(x, cross, out, 0);   // pooled jobs
    cudaEventRecord(e1, s2);

    attn_mma<<<400, 192, SMEM_TOTAL>>>(x, cross, out, 96);     // raw jobs

    cudaStreamWaitEvent(0, e1, 0);
    {
        int total = 400 * (LC / 4);
        combine<<<(total + 255) / 256, 256>>>(out);
    }
}